// round 16
// baseline (speedup 1.0000x reference)
#include <cuda_runtime.h>
#include <cuda_fp16.h>
#include <math.h>

#define NNODES 100000
#define NEDGES 1600000
#define FIN 128
#define FOUT 64
#define SCAN_NB ((NNODES + 1023) / 1024)   // 98

typedef unsigned int u32;
typedef unsigned long long u64;

// ---------------- scratch (device globals; 16B-aligned) ----------------
__device__ __align__(16) int     g_ecnt[NNODES];
__device__ __align__(16) int     g_incl[NNODES];
__device__ __align__(16) int     g_bsum[SCAN_NB];
__device__ __align__(16) int     g_rowptr[NNODES + 1];
__device__ __align__(16) int     g_cursor[NNODES];
__device__ __align__(16) int     g_col[NEDGES];
__device__ __align__(16) float   g_dinv[NNODES];
__device__ __align__(16) __half2 g_h[NNODES * (FOUT / 2)];   // (x@W)*dinv, fp16 gather table
__device__ __align__(16) float   g_t1[NNODES * FOUT];        // x_temp (residual, fp32)
__device__ __align__(16) float   g_t2[NNODES * FOUT];        // layer-2 activation (fp32)
__device__ int g_is64;

// ---------------- zero + dtype detect (fused; block 0 detects) ----------------
__global__ void k_zero(const void* __restrict__ ei) {
    int i = blockIdx.x * blockDim.x + threadIdx.x;
    if (i < NNODES) g_ecnt[i] = 0;
    if (blockIdx.x == 0) {
        const unsigned long long* p = (const unsigned long long*)ei;
        __shared__ unsigned int s;
        if (threadIdx.x == 0) s = 0u;
        __syncthreads();
        unsigned int any = 0u;
        for (int j = threadIdx.x; j < 4096; j += blockDim.x)
            any |= (unsigned int)(p[j] >> 32);
        atomicOr(&s, any);
        __syncthreads();
        if (threadIdx.x == 0) g_is64 = (s == 0u) ? 1 : 0;
    }
}

__device__ __forceinline__ int load_idx(const int* __restrict__ ei32, long long pos) {
    if (g_is64) return (int)((const long long*)ei32)[pos];
    return ei32[pos];
}

// ---------------- CSR build (R13 measured-best structure) ----------------
__global__ void k_count(const int* __restrict__ ei32) {
    int e = blockIdx.x * blockDim.x + threadIdx.x;
    if (e < NEDGES) {
        int d = load_idx(ei32, (long long)NEDGES + e);
        if ((unsigned)d < (unsigned)NNODES) atomicAdd(&g_ecnt[d], 1);
    }
}

__global__ __launch_bounds__(1024) void k_scan1() {
    __shared__ int wsum[32];
    const int i    = blockIdx.x * 1024 + threadIdx.x;
    const int lane = threadIdx.x & 31;
    const int warp = threadIdx.x >> 5;
    int v = (i < NNODES) ? g_ecnt[i] : 0;
    int x = v;
#pragma unroll
    for (int o = 1; o < 32; o <<= 1) {
        int y = __shfl_up_sync(0xffffffffu, x, o);
        if (lane >= o) x += y;
    }
    if (lane == 31) wsum[warp] = x;
    __syncthreads();
    if (warp == 0) {
        int s = wsum[lane];
#pragma unroll
        for (int o = 1; o < 32; o <<= 1) {
            int y = __shfl_up_sync(0xffffffffu, s, o);
            if (lane >= o) s += y;
        }
        wsum[lane] = s;
    }
    __syncthreads();
    int incl = x + (warp > 0 ? wsum[warp - 1] : 0);
    if (i < NNODES) g_incl[i] = incl;
    if (threadIdx.x == 1023) g_bsum[blockIdx.x] = incl;
}

__global__ void k_scan2() {
    __shared__ int s[128];
    const int t = threadIdx.x;
    s[t] = (t < SCAN_NB) ? g_bsum[t] : 0;
    __syncthreads();
    for (int o = 1; o < 128; o <<= 1) {
        int x = s[t];
        int add = (t >= o) ? s[t - o] : 0;
        __syncthreads();
        s[t] = x + add;
        __syncthreads();
    }
    if (t < SCAN_NB) g_bsum[t] = (t == 0) ? 0 : s[t - 1];
    if (t == 0) g_rowptr[NNODES] = s[SCAN_NB - 1];
}

__global__ __launch_bounds__(1024) void k_scan3() {
    const int i = blockIdx.x * 1024 + threadIdx.x;
    if (i < NNODES) {
        int c = g_ecnt[i];
        int start = g_bsum[blockIdx.x] + g_incl[i] - c;
        g_rowptr[i] = start;
        g_cursor[i] = start;
        g_dinv[i]   = rsqrtf((float)(c + 1));
    }
}

__global__ void k_fill(const int* __restrict__ ei32) {
    int e = blockIdx.x * blockDim.x + threadIdx.x;
    if (e < NEDGES) {
        int d = load_idx(ei32, (long long)NEDGES + e);
        int s = load_idx(ei32, e);
        if ((unsigned)d < (unsigned)NNODES && (unsigned)s < (unsigned)NNODES) {
            int p = atomicAdd(&g_cursor[d], 1);
            g_col[p] = s;
        }
    }
}

// ---------------- HMMA GEMM (single-stage, dynamic smem) ----------------
// g_h[n,:] = half((X[n,:] @ W) * dinv[n]); whole K tile staged at once.
// ASTR = K+8 halfs (frag loads bank-conflict-free: row stride (K+8)/2 words).
template <int K, int SEL>
__global__ __launch_bounds__(256) void k_gemm(const float* __restrict__ Xext,
                                              const float* __restrict__ W) {
    constexpr int ASTR = K + 8;
    extern __shared__ __align__(16) __half sm[];
    __half* Asm = sm;                       // 128 x ASTR
    __half* Bsm = sm + 128 * ASTR;          // 64 x ASTR

    const float* X;
    if constexpr (SEL == 0)      X = Xext;
    else if constexpr (SEL == 1) X = g_t1;
    else                         X = g_t2;

    const int tid  = threadIdx.x;
    const int warp = tid >> 5;
    const int lane = tid & 31;
    const int base = blockIdx.x * 128;
    const int wrow = warp * 16;
    const int qrow = lane >> 2;          // 0..7
    const int qk   = (lane & 3) * 2;     // 0,2,4,6

    // stage A: 128 nodes x K, fp32 -> fp16 (float4-granular, MLP = K/8 per thread)
    constexpr int C4 = K / 4;
    for (int i = tid; i < 128 * C4; i += 256) {
        int r = i / C4, c4 = (i % C4) * 4;
        int node = base + r;
        float4 v = make_float4(0.f, 0.f, 0.f, 0.f);
        if (node < NNODES)
            v = *(const float4*)&X[(size_t)node * K + c4];
        __half2 h0 = __floats2half2_rn(v.x, v.y);
        __half2 h1 = __floats2half2_rn(v.z, v.w);
        u32 w0 = *(u32*)&h0, w1 = *(u32*)&h1;
        *(u64*)&Asm[r * ASTR + c4] = ((u64)w1 << 32) | (u64)w0;
    }
    // stage B transposed: Bsm[n][k] = W[k][n]
    for (int i = tid; i < 64 * K; i += 256) {
        int k = i >> 6, n = i & 63;
        Bsm[n * ASTR + k] = __float2half_rn(W[(size_t)k * FOUT + n]);
    }
    __syncthreads();

    float acc[8][4];
#pragma unroll
    for (int t = 0; t < 8; t++)
#pragma unroll
        for (int j = 0; j < 4; j++) acc[t][j] = 0.f;

#pragma unroll
    for (int s = 0; s < K / 16; s++) {
        const int k0 = s * 16;
        u32 a0 = *(const u32*)&Asm[(wrow + qrow)     * ASTR + k0 + qk];
        u32 a1 = *(const u32*)&Asm[(wrow + qrow + 8) * ASTR + k0 + qk];
        u32 a2 = *(const u32*)&Asm[(wrow + qrow)     * ASTR + k0 + qk + 8];
        u32 a3 = *(const u32*)&Asm[(wrow + qrow + 8) * ASTR + k0 + qk + 8];
#pragma unroll
        for (int t = 0; t < 8; t++) {
            u32 b0 = *(const u32*)&Bsm[(8 * t + qrow) * ASTR + k0 + qk];
            u32 b1 = *(const u32*)&Bsm[(8 * t + qrow) * ASTR + k0 + qk + 8];
            asm volatile(
                "mma.sync.aligned.m16n8k16.row.col.f32.f16.f16.f32 "
                "{%0,%1,%2,%3}, {%4,%5,%6,%7}, {%8,%9}, {%0,%1,%2,%3};"
                : "+f"(acc[t][0]), "+f"(acc[t][1]), "+f"(acc[t][2]), "+f"(acc[t][3])
                : "r"(a0), "r"(a1), "r"(a2), "r"(a3), "r"(b0), "r"(b1));
        }
    }

    const int nlo = base + wrow + qrow;
    const int nhi = nlo + 8;
    const float dlo = (nlo < NNODES) ? g_dinv[nlo] : 0.f;
    const float dhi = (nhi < NNODES) ? g_dinv[nhi] : 0.f;
    const int cp = lane & 3;
#pragma unroll
    for (int t = 0; t < 8; t++) {
        int col = t * 4 + cp;
        if (nlo < NNODES)
            g_h[(size_t)nlo * 32 + col] = __floats2half2_rn(acc[t][0] * dlo, acc[t][1] * dlo);
        if (nhi < NNODES)
            g_h[(size_t)nhi * 32 + col] = __floats2half2_rn(acc[t][2] * dhi, acc[t][3] * dhi);
    }
}

// ---------------- aggregation: 2 warps per node, MLP=16 per warp ----------------
// Block = 8 warps = 4 nodes (grid 25000, exact). Warp pair splits the edge list;
// sub-warp 1 deposits its partial in smem; named bar.sync(pair+1, 64); sub 0 merges.
// MODE 0: identity -> g_t1 | MODE 1: relu -> g_t2 | MODE 2: relu + g_t1 -> ext out
template <int MODE>
__global__ __launch_bounds__(256) void k_agg(const float* __restrict__ bias,
                                             float* __restrict__ outext) {
    __shared__ float2 sh[4][32];
    const int warp = threadIdx.x >> 5;
    const int lane = threadIdx.x & 31;
    const int pair = warp >> 1;          // 0..3
    const int sub  = warp & 1;
    const int node = blockIdx.x * 4 + pair;   // NNODES % 4 == 0

    float* out;
    if constexpr (MODE == 0)      out = g_t1;
    else if constexpr (MODE == 1) out = g_t2;
    else                          out = outext;

    const int beg  = g_rowptr[node];
    const int end  = g_rowptr[node + 1];
    const int half = (end - beg + 1) >> 1;
    const int p0   = sub ? beg + half : beg;
    const int p1   = sub ? end        : beg + half;

    float2 acc = {0.f, 0.f};
    if (sub == 0) acc = __half22float2(g_h[(size_t)node * 32 + lane]);   // self-loop

    int p = p0;
    for (; p + 16 <= p1; p += 16) {
        int sx[16];
#pragma unroll
        for (int j = 0; j < 16; j++) sx[j] = g_col[p + j];
        __half2 h[16];
#pragma unroll
        for (int j = 0; j < 16; j++) h[j] = g_h[(size_t)sx[j] * 32 + lane];
        float sx0 = 0.f, sy0 = 0.f, sx1 = 0.f, sy1 = 0.f;
#pragma unroll
        for (int j = 0; j < 16; j += 2) {
            float2 f0 = __half22float2(h[j]);
            float2 f1 = __half22float2(h[j + 1]);
            sx0 += f0.x; sy0 += f0.y;
            sx1 += f1.x; sy1 += f1.y;
        }
        acc.x += sx0 + sx1;
        acc.y += sy0 + sy1;
    }
    for (; p + 8 <= p1; p += 8) {
        int s0 = g_col[p],     s1 = g_col[p + 1], s2 = g_col[p + 2], s3 = g_col[p + 3];
        int s4 = g_col[p + 4], s5 = g_col[p + 5], s6 = g_col[p + 6], s7 = g_col[p + 7];
        __half2 h0 = g_h[(size_t)s0 * 32 + lane];
        __half2 h1 = g_h[(size_t)s1 * 32 + lane];
        __half2 h2 = g_h[(size_t)s2 * 32 + lane];
        __half2 h3 = g_h[(size_t)s3 * 32 + lane];
        __half2 h4 = g_h[(size_t)s4 * 32 + lane];
        __half2 h5 = g_h[(size_t)s5 * 32 + lane];
        __half2 h6 = g_h[(size_t)s6 * 32 + lane];
        __half2 h7 = g_h[(size_t)s7 * 32 + lane];
        float2 b0 = __half22float2(h0), b1 = __half22float2(h1);
        float2 b2 = __half22float2(h2), b3 = __half22float2(h3);
        float2 b4 = __half22float2(h4), b5 = __half22float2(h5);
        float2 b6 = __half22float2(h6), b7 = __half22float2(h7);
        acc.x += ((b0.x + b1.x) + (b2.x + b3.x)) + ((b4.x + b5.x) + (b6.x + b7.x));
        acc.y += ((b0.y + b1.y) + (b2.y + b3.y)) + ((b4.y + b5.y) + (b6.y + b7.y));
    }
    for (; p + 4 <= p1; p += 4) {
        int s0 = g_col[p], s1 = g_col[p + 1], s2 = g_col[p + 2], s3 = g_col[p + 3];
        float2 b0 = __half22float2(g_h[(size_t)s0 * 32 + lane]);
        float2 b1 = __half22float2(g_h[(size_t)s1 * 32 + lane]);
        float2 b2 = __half22float2(g_h[(size_t)s2 * 32 + lane]);
        float2 b3 = __half22float2(g_h[(size_t)s3 * 32 + lane]);
        acc.x += (b0.x + b1.x) + (b2.x + b3.x);
        acc.y += (b0.y + b1.y) + (b2.y + b3.y);
    }
    for (; p < p1; p++) {
        int s = g_col[p];
        float2 b = __half22float2(g_h[(size_t)s * 32 + lane]);
        acc.x += b.x; acc.y += b.y;
    }

    if (sub == 1) sh[pair][lane] = acc;
    asm volatile("bar.sync %0, 64;" :: "r"(pair + 1) : "memory");
    if (sub == 0) {
        float2 o = sh[pair][lane];
        acc.x += o.x; acc.y += o.y;

        const int off = 2 * lane;
        const float di = g_dinv[node];
        float2 bb = *(const float2*)&bias[off];
        float rx = fmaf(di, acc.x, bb.x);
        float ry = fmaf(di, acc.y, bb.y);
        if (MODE >= 1) { rx = fmaxf(rx, 0.f); ry = fmaxf(ry, 0.f); }
        if (MODE == 2) {
            float2 r = *(const float2*)&g_t1[(size_t)node * FOUT + off];
            rx += r.x; ry += r.y;
        }
        *(float2*)&out[(size_t)node * FOUT + off] = make_float2(rx, ry);
    }
}

// ---------------- launch ----------------
extern "C" void kernel_launch(void* const* d_in, const int* in_sizes, int n_in,
                              void* d_out, int out_size) {
    const float* x  = (const float*)d_in[0];
    const int*   ei = (const int*)d_in[1];     // int32 or int64; detected on device
    const float* W0 = (const float*)d_in[2];
    const float* b0 = (const float*)d_in[3];
    const float* Ws = (const float*)d_in[4];
    const float* bs = (const float*)d_in[5];
    float*       out = (float*)d_out;

    const int NB_N  = (NNODES + 255) / 256;
    const int NB_E  = (NEDGES + 255) / 256;
    const int NB_T  = (NNODES + 127) / 128;   // 782 GEMM tiles
    const int NB_A  = NNODES / 4;             // 25000 (exact)
    const int SM128 = 192 * (FIN + 8) * 2;    // 52224 B
    const int SM64  = 192 * (FOUT + 8) * 2;   // 27648 B

    cudaFuncSetAttribute(k_gemm<FIN, 0>,  cudaFuncAttributeMaxDynamicSharedMemorySize, SM128);
    cudaFuncSetAttribute(k_gemm<FOUT, 1>, cudaFuncAttributeMaxDynamicSharedMemorySize, SM64);
    cudaFuncSetAttribute(k_gemm<FOUT, 2>, cudaFuncAttributeMaxDynamicSharedMemorySize, SM64);

    // CSR build (per call; deterministic)
    k_zero  <<<NB_N, 256>>>(ei);             // fused dtype detect (block 0)
    k_count <<<NB_E, 256>>>(ei);
    k_scan1 <<<SCAN_NB, 1024>>>();
    k_scan2 <<<1, 128>>>();
    k_scan3 <<<SCAN_NB, 1024>>>();
    k_fill  <<<NB_E, 256>>>(ei);

    // layer 1: t1 = conv(x, W0, b0)
    k_gemm<FIN, 0> <<<NB_T, 256, SM128>>>(x, W0);
    k_agg<0>       <<<NB_A, 256>>>(b0, nullptr);

    // layer 2: t2 = relu(conv(t1, Ws[0], bs[0]))
    k_gemm<FOUT, 1><<<NB_T, 256, SM64>>>(nullptr, Ws);
    k_agg<1>       <<<NB_A, 256>>>(bs, nullptr);

    // layer 3: out = relu(conv(t2, Ws[1], bs[1])) + t1
    k_gemm<FOUT, 2><<<NB_T, 256, SM64>>>(nullptr, Ws + FOUT * FOUT);
    k_agg<2>       <<<NB_A, 256>>>(bs + FOUT, out);
}